// round 15
// baseline (speedup 1.0000x reference)
#include <cuda_runtime.h>
#include <cuda_fp16.h>
#include <cstdint>

// Problem constants
#define Bdim 8
#define Nseq 2048
#define Edim 1024
#define Hh   16
#define Dd   64
#define Mrows (Bdim * Nseq)      // 16384

// ---------------------------------------------------------------------------
// Scratch (allocation-free rule: __device__ globals)
// ---------------------------------------------------------------------------
__device__ __half  g_qkvh[(size_t)Mrows * 3 * Edim];  // 96 MB fp16 qkv
__device__ __half  g_xh [(size_t)Mrows * Edim];       // x as fp16
__device__ __half  g_ath[(size_t)Mrows * Edim];       // attn out as fp16
__device__ __half  g_wqh[(size_t)3 * Edim * Edim];    // Wqkv fp16
__device__ __half  g_woh[(size_t)Edim * Edim];        // Wo fp16

// ---------------------------------------------------------------------------
// Helpers (baseline-feature PTX only: cp.async, ldmatrix, mma.sync — sm_80+)
// ---------------------------------------------------------------------------
__device__ __forceinline__ uint32_t smem_u32(const void* p) {
    uint32_t a;
    asm("{ .reg .u64 t; cvta.to.shared.u64 t, %1; cvt.u32.u64 %0, t; }" : "=r"(a) : "l"(p));
    return a;
}
#define SWZ(x) ((x) ^ (((x) >> 3) & 0x70))

__device__ __forceinline__ void cp16(uint32_t dst, const void* src) {
    asm volatile("cp.async.cg.shared.global [%0], [%1], 16;" :: "r"(dst), "l"(src));
}
__device__ __forceinline__ void ldm4(uint32_t* r, uint32_t addr) {
    asm volatile("ldmatrix.sync.aligned.m8n8.x4.shared.b16 {%0,%1,%2,%3}, [%4];"
                 : "=r"(r[0]), "=r"(r[1]), "=r"(r[2]), "=r"(r[3]) : "r"(addr));
}
__device__ __forceinline__ void mma_f16(float* c, const uint32_t* a, uint32_t b0, uint32_t b1) {
    asm volatile(
        "mma.sync.aligned.m16n8k16.row.col.f32.f16.f16.f32 "
        "{%0,%1,%2,%3}, {%4,%5,%6,%7}, {%8,%9}, {%0,%1,%2,%3};"
        : "+f"(c[0]), "+f"(c[1]), "+f"(c[2]), "+f"(c[3])
        : "r"(a[0]), "r"(a[1]), "r"(a[2]), "r"(a[3]), "r"(b0), "r"(b1));
}

// ---------------------------------------------------------------------------
// fp32 -> fp16 conversion kernel
// ---------------------------------------------------------------------------
__global__ __launch_bounds__(256)
void tohalf_kernel(const float4* __restrict__ src, uint2* __restrict__ dst, int n4)
{
    int i = blockIdx.x * 256 + threadIdx.x;
    if (i >= n4) return;
    float4 v = src[i];
    __half2 p0 = __floats2half2_rn(v.x, v.y);
    __half2 p1 = __floats2half2_rn(v.z, v.w);
    uint2 u;
    u.x = *(uint32_t*)&p0; u.y = *(uint32_t*)&p1;
    dst[i] = u;
}

// ---------------------------------------------------------------------------
// fp16 NT GEMM via mma.sync: C[M,N] = A[M,K] @ B[N,K]^T + bias[N].
// CTA tile 128x128, 128 threads (4 warps 2x2, 64x64 per warp), K-slab 64.
// 3-stage cp.async ring (32KB/stage: A 16KB | B 16KB, SW128 rows), 2 CTAs/SM.
// 64x64 warp tiles: 8 ldm4 per 32 HMMA (ratio 4.0, -33% LDSM traffic vs
// 32x64). CTA-pair interleave covers barrier/LDSM phases.
// ---------------------------------------------------------------------------
#define STG_BYTES 32768
#define GSMEM (3 * STG_BYTES + 1024)
#define NTHREADS 128

template<bool HALF_OUT>
__global__ __launch_bounds__(NTHREADS, 2)
void gemm_mma(const __half* __restrict__ A, const __half* __restrict__ B,
              const float* __restrict__ bias, void* __restrict__ Cv, int N)
{
    extern __shared__ char smem_raw[];
    const uint32_t sb = (smem_u32(smem_raw) + 1023) & ~1023u;
    const int tid  = threadIdx.x;
    const int lane = tid & 31;
    const int wid  = tid >> 5;
    const int wm   = wid >> 1;          // 0..1  (M, 64 rows)
    const int wn   = wid & 1;           // 0..1  (N, 64 cols)
    const int brow = blockIdx.y * 128;
    const int bcol = blockIdx.x * 128;

    float acc[4][8][4];
#pragma unroll
    for (int i = 0; i < 4; i++)
#pragma unroll
        for (int j = 0; j < 8; j++)
#pragma unroll
            for (int k = 0; k < 4; k++) acc[i][j][k] = 0.f;

    const int  lrow   = lane & 15;
    const int  lkb    = (lane >> 4) * 16;
    const uint32_t a_base = SWZ((wm * 64 + lrow) * 128 + lkb);
    const uint32_t b_base = SWZ((wn * 64 + lrow) * 128 + lkb);

    // ---- cp.async addressing: 16 chunks/thread/slab (8 A + 8 B) ----
    const int r0 = tid >> 3;            // 0..15
    const int c8 = (tid & 7) * 8;
    const __half* aptr = A + (size_t)(brow + r0) * Edim + c8;
    const __half* bptr = B + (size_t)(bcol + r0) * Edim + c8;
    const uint32_t saw = SWZ(r0 * 128 + (tid & 7) * 16);
    const uint32_t sa0 = sb + saw;
    const uint32_t sb0 = sb + 16384 + saw;

    // full-stage load (prologue)
    auto load_stage = [&](uint32_t bo) {
#pragma unroll
        for (int j = 0; j < 8; j++) {
            cp16(sa0 + bo + j * 2048, aptr + (size_t)j * 16 * Edim);
            cp16(sb0 + bo + j * 2048, bptr + (size_t)j * 16 * Edim);
        }
        asm volatile("cp.async.commit_group;");
        aptr += 64;
        bptr += 64;
    };

    load_stage(0);
    load_stage(STG_BYTES);

    auto a_addr = [&](uint32_t stg, int kk, int mt) {
        return stg + ((a_base + mt * 2048) ^ ((uint32_t)kk * 32));
    };
    auto b_addr = [&](uint32_t stg, int kk, int p) {
        return stg + 16384 + ((b_base + p * 2048) ^ ((uint32_t)kk * 32));
    };

    uint32_t a[4][4], b[4][4];

    for (int s = 0; s < 16; ++s) {
        if (s < 15) asm volatile("cp.async.wait_group 1;");
        else        asm volatile("cp.async.wait_group 0;");
        __syncthreads();

        const uint32_t stg = sb + (uint32_t)(s % 3) * STG_BYTES;
        const uint32_t nbo = (uint32_t)((s + 2) % 3) * STG_BYTES;
        const bool more = (s < 14);

#pragma unroll
        for (int kk = 0; kk < 4; kk++) {
            // spread next-next-stage cp.async: 4 chunks per kk
            if (more) {
#pragma unroll
                for (int t = 0; t < 4; t++) {
                    const int i = kk * 4 + t;
                    if (i < 8) cp16(sa0 + nbo + i * 2048, aptr + (size_t)i * 16 * Edim);
                    else       cp16(sb0 + nbo + (i - 8) * 2048, bptr + (size_t)(i - 8) * 16 * Edim);
                }
            }
#pragma unroll
            for (int mt = 0; mt < 4; mt++) ldm4(a[mt], a_addr(stg, kk, mt));
#pragma unroll
            for (int p = 0; p < 4; p++)    ldm4(b[p], b_addr(stg, kk, p));
#pragma unroll
            for (int p = 0; p < 4; p++)
#pragma unroll
                for (int q = 0; q < 2; q++) {
                    const int nt = 2 * p + q;
#pragma unroll
                    for (int mt = 0; mt < 4; mt++)
                        mma_f16(acc[mt][nt], a[mt], b[p][q], b[p][q + 2]);
                }
        }
        if (more) {
            asm volatile("cp.async.commit_group;");
            aptr += 64;
            bptr += 64;
        }
    }

    // ---- epilogue: bias add ----
    const int g  = lane >> 2;
    const int q2 = (lane & 3) * 2;
#pragma unroll
    for (int mt = 0; mt < 4; mt++) {
#pragma unroll
        for (int h = 0; h < 2; h++) {
            const int row = brow + wm * 64 + mt * 16 + g + h * 8;
#pragma unroll
            for (int nt = 0; nt < 8; nt++) {
                const int col = bcol + wn * 64 + nt * 8 + q2;
                const float vx = acc[mt][nt][2 * h + 0] + __ldg(bias + col + 0);
                const float vy = acc[mt][nt][2 * h + 1] + __ldg(bias + col + 1);
                if (HALF_OUT) {
                    __half2 hv = __floats2half2_rn(vx, vy);
                    *(uint32_t*)((__half*)Cv + (size_t)row * N + col) = *(uint32_t*)&hv;
                } else {
                    float2 v2 = make_float2(vx, vy);
                    *(float2*)((float*)Cv + (size_t)row * N + col) = v2;
                }
            }
        }
    }
}

// ---------------------------------------------------------------------------
// Per-position "head attention" (einsum-label bug replicated exactly).
// Reads fp16 qkv, computes in fp32, emits fp16 output.
// ---------------------------------------------------------------------------
__global__ __launch_bounds__(256)
void attn_kernel(const __half* __restrict__ qkv, __half* __restrict__ oh)
{
    __shared__ __align__(16) float s[3 * Edim];
    __shared__ float en[Hh][Hh + 1];
    __shared__ float rinv[Hh];

    const int bp  = blockIdx.x;
    const int b   = bp >> 11;
    const int pos = bp & 2047;
    const int tid = threadIdx.x;

    {
        const uint2* r2 = (const uint2*)(qkv + (size_t)bp * 3072);
        float4* s4 = (float4*)s;
#pragma unroll
        for (int t = 0; t < 3; t++) {
            const int idx = tid + t * 256;
            uint2 u = r2[idx];
            __half2 h0 = *(__half2*)&u.x;
            __half2 h1 = *(__half2*)&u.y;
            float2 f0 = __half22float2(h0);
            float2 f1 = __half22float2(h1);
            s4[idx] = make_float4(f0.x, f0.y, f1.x, f1.y);
        }
    }
    __syncthreads();

    {
        const int i = tid >> 4;
        const int j = tid & 15;
        const float* q  = s + i * 64;
        const float* kp = s + 1024 + j * 64;
        float e = 0.f;
#pragma unroll
        for (int dd = 0; dd < 16; dd++) {
            const int d4 = ((dd + tid) & 15) * 4;
            float4 qv = *(const float4*)(q + d4);
            float4 kv = *(const float4*)(kp + d4);
            e += qv.x * kv.x + qv.y * kv.y + qv.z * kv.z + qv.w * kv.w;
        }
        en[i][j] = e * 0.03125f;   // 1/sqrt(1024)
    }
    __syncthreads();

    if (tid < Hh) {
        float m = -1e30f;
#pragma unroll
        for (int j = 0; j < Hh; j++) m = fmaxf(m, en[tid][j]);
        float sum = 0.f;
#pragma unroll
        for (int j = 0; j < Hh; j++) {
            const float v = __expf(en[tid][j] - m);
            en[tid][j] = v;
            sum += v;
        }
        rinv[tid] = 1.f / sum;
    }
    __syncthreads();

#pragma unroll
    for (int t0 = 0; t0 < 4; t0++) {
        const int t = tid + t0 * 256;
        const int i = t >> 6;
        const int d = t & 63;
        float o = 0.f;
#pragma unroll
        for (int l = 0; l < Hh; l++)
            o += en[i][l] * s[2048 + l * 64 + d];
        o *= rinv[i];
        const size_t idx = ((size_t)(b * Hh + i) * Nseq + pos) * Dd + d;
        oh[idx] = __float2half_rn(o);
    }
}

// ---------------------------------------------------------------------------
// launch
// ---------------------------------------------------------------------------
extern "C" void kernel_launch(void* const* d_in, const int* in_sizes, int n_in,
                              void* d_out, int out_size)
{
    const float* x    = (const float*)d_in[0];   // [16384,1024]
    const float* Wqkv = (const float*)d_in[1];   // [3072,1024]
    const float* bqkv = (const float*)d_in[2];
    const float* Wo   = (const float*)d_in[3];   // [1024,1024]
    const float* bo   = (const float*)d_in[4];
    float* out = (float*)d_out;

    __half *qkvh, *xh, *ath, *wqh, *woh;
    cudaGetSymbolAddress((void**)&qkvh, g_qkvh);
    cudaGetSymbolAddress((void**)&xh,  g_xh);
    cudaGetSymbolAddress((void**)&ath, g_ath);
    cudaGetSymbolAddress((void**)&wqh, g_wqh);
    cudaGetSymbolAddress((void**)&woh, g_woh);

    cudaFuncSetAttribute(gemm_mma<true>,  cudaFuncAttributeMaxDynamicSharedMemorySize, GSMEM);
    cudaFuncSetAttribute(gemm_mma<false>, cudaFuncAttributeMaxDynamicSharedMemorySize, GSMEM);

    // 0) x, Wqkv, Wo -> fp16
    {
        int n4 = Mrows * Edim / 4;
        tohalf_kernel<<<(n4 + 255) / 256, 256>>>((const float4*)x, (uint2*)xh, n4);
        n4 = 3 * Edim * Edim / 4;
        tohalf_kernel<<<(n4 + 255) / 256, 256>>>((const float4*)Wqkv, (uint2*)wqh, n4);
        n4 = Edim * Edim / 4;
        tohalf_kernel<<<(n4 + 255) / 256, 256>>>((const float4*)Wo, (uint2*)woh, n4);
    }

    // 1) qkv = x @ Wqkv^T + bqkv   [16384, 3072]  (fp16 out)
    {
        dim3 grid(3 * Edim / 128, Mrows / 128);
        gemm_mma<true><<<grid, NTHREADS, GSMEM>>>(xh, wqh, bqkv, qkvh, 3 * Edim);
    }

    // 2) per-position head-attention -> fp16 in raw [B,H,N,D] layout
    attn_kernel<<<Mrows, 256>>>(qkvh, ath);

    // 3) out = Y @ Wo^T + bo   [16384, 1024]  (fp32 out)
    {
        dim3 grid(Edim / 128, Mrows / 128);
        gemm_mma<false><<<grid, NTHREADS, GSMEM>>>(ath, woh, bo, out, Edim);
    }
}

// round 16
// speedup vs baseline: 1.0361x; 1.0361x over previous
#include <cuda_runtime.h>
#include <cuda_fp16.h>
#include <cstdint>

// Problem constants
#define Bdim 8
#define Nseq 2048
#define Edim 1024
#define Hh   16
#define Dd   64
#define Mrows (Bdim * Nseq)      // 16384

// ---------------------------------------------------------------------------
// Scratch (allocation-free rule: __device__ globals)
// ---------------------------------------------------------------------------
__device__ __half  g_qkvh[(size_t)Mrows * 3 * Edim];  // 96 MB fp16 qkv
__device__ __half  g_xh [(size_t)Mrows * Edim];       // x as fp16
__device__ __half  g_ath[(size_t)Mrows * Edim];       // attn out as fp16
__device__ __half  g_wqh[(size_t)3 * Edim * Edim];    // Wqkv fp16
__device__ __half  g_woh[(size_t)Edim * Edim];        // Wo fp16

// ---------------------------------------------------------------------------
// Helpers (baseline-feature PTX only: cp.async, ldmatrix, mma.sync — sm_80+)
// ---------------------------------------------------------------------------
__device__ __forceinline__ uint32_t smem_u32(const void* p) {
    uint32_t a;
    asm("{ .reg .u64 t; cvta.to.shared.u64 t, %1; cvt.u32.u64 %0, t; }" : "=r"(a) : "l"(p));
    return a;
}
#define SWZ(x) ((x) ^ (((x) >> 3) & 0x70))

__device__ __forceinline__ void cp16(uint32_t dst, const void* src) {
    asm volatile("cp.async.cg.shared.global [%0], [%1], 16;" :: "r"(dst), "l"(src));
}
__device__ __forceinline__ void ldm4(uint32_t* r, uint32_t addr) {
    asm volatile("ldmatrix.sync.aligned.m8n8.x4.shared.b16 {%0,%1,%2,%3}, [%4];"
                 : "=r"(r[0]), "=r"(r[1]), "=r"(r[2]), "=r"(r[3]) : "r"(addr));
}
__device__ __forceinline__ void mma_f16(float* c, const uint32_t* a, uint32_t b0, uint32_t b1) {
    asm volatile(
        "mma.sync.aligned.m16n8k16.row.col.f32.f16.f16.f32 "
        "{%0,%1,%2,%3}, {%4,%5,%6,%7}, {%8,%9}, {%0,%1,%2,%3};"
        : "+f"(c[0]), "+f"(c[1]), "+f"(c[2]), "+f"(c[3])
        : "r"(a[0]), "r"(a[1]), "r"(a[2]), "r"(a[3]), "r"(b0), "r"(b1));
}

// ---------------------------------------------------------------------------
// fp32 -> fp16 conversion, single launch, 3 segments (x | Wqkv | Wo)
// ---------------------------------------------------------------------------
#define N4_X  (Mrows * Edim / 4)          // 4194304
#define N4_WQ (3 * Edim * Edim / 4)       // 786432
#define N4_WO (Edim * Edim / 4)           // 262144
#define N4_TOTAL (N4_X + N4_WQ + N4_WO)

__global__ __launch_bounds__(256)
void tohalf3_kernel(const float4* __restrict__ sx, uint2* __restrict__ dx,
                    const float4* __restrict__ sq, uint2* __restrict__ dq,
                    const float4* __restrict__ so, uint2* __restrict__ dw)
{
    int i = blockIdx.x * 256 + threadIdx.x;
    const float4* src;
    uint2* dst;
    if (i < N4_X)                { src = sx; dst = dx; }
    else if (i < N4_X + N4_WQ)   { src = sq; dst = dq; i -= N4_X; }
    else if (i < N4_TOTAL)       { src = so; dst = dw; i -= (N4_X + N4_WQ); }
    else return;
    float4 v = src[i];
    __half2 p0 = __floats2half2_rn(v.x, v.y);
    __half2 p1 = __floats2half2_rn(v.z, v.w);
    uint2 u;
    u.x = *(uint32_t*)&p0; u.y = *(uint32_t*)&p1;
    dst[i] = u;
}

// ---------------------------------------------------------------------------
// fp16 NT GEMM via mma.sync (REVERTED to R14 best config):
// CTA tile 128x128, 256 threads (8 warps 4x2, 32x64 per warp), K-slab 64.
// 3-stage cp.async ring (32KB/stage), 2 CTAs/SM so the two CTAs' load and
// compute phases interleave across slab barriers.
// ---------------------------------------------------------------------------
#define STG_BYTES 32768
#define GSMEM (3 * STG_BYTES + 1024)
#define NTHREADS 256

template<bool HALF_OUT>
__global__ __launch_bounds__(NTHREADS, 2)
void gemm_mma(const __half* __restrict__ A, const __half* __restrict__ B,
              const float* __restrict__ bias, void* __restrict__ Cv, int N)
{
    extern __shared__ char smem_raw[];
    const uint32_t sb = (smem_u32(smem_raw) + 1023) & ~1023u;
    const int tid  = threadIdx.x;
    const int lane = tid & 31;
    const int wid  = tid >> 5;
    const int wm   = wid >> 1;          // 0..3  (M, 32 rows)
    const int wn   = wid & 1;           // 0..1  (N, 64 cols)
    const int brow = blockIdx.y * 128;
    const int bcol = blockIdx.x * 128;

    float acc[2][8][4];
#pragma unroll
    for (int i = 0; i < 2; i++)
#pragma unroll
        for (int j = 0; j < 8; j++)
#pragma unroll
            for (int k = 0; k < 4; k++) acc[i][j][k] = 0.f;

    const int  lrow   = lane & 15;
    const int  lkb    = (lane >> 4) * 16;
    const uint32_t a_base = SWZ((wm * 32 + lrow) * 128 + lkb);
    const uint32_t b_base = SWZ((wn * 64 + lrow) * 128 + lkb);

    // ---- cp.async addressing: 8 chunks/thread/slab (4 A + 4 B) ----
    const int r0 = tid >> 3;            // 0..31
    const int c8 = (tid & 7) * 8;
    const __half* aptr = A + (size_t)(brow + r0) * Edim + c8;
    const __half* bptr = B + (size_t)(bcol + r0) * Edim + c8;
    const uint32_t saw = SWZ(r0 * 128 + (tid & 7) * 16);
    const uint32_t sa0 = sb + saw;
    const uint32_t sb0 = sb + 16384 + saw;

    auto load_stage = [&](uint32_t bo) {
#pragma unroll
        for (int j = 0; j < 4; j++) {
            cp16(sa0 + bo + j * 4096, aptr + (size_t)j * 32 * Edim);
            cp16(sb0 + bo + j * 4096, bptr + (size_t)j * 32 * Edim);
        }
        asm volatile("cp.async.commit_group;");
        aptr += 64;
        bptr += 64;
    };

    load_stage(0);
    load_stage(STG_BYTES);

    auto a_addr = [&](uint32_t stg, int kk, int mt) {
        return stg + ((a_base + mt * 2048) ^ ((uint32_t)kk * 32));
    };
    auto b_addr = [&](uint32_t stg, int kk, int p) {
        return stg + 16384 + ((b_base + p * 2048) ^ ((uint32_t)kk * 32));
    };

    uint32_t a[2][2][4];   // [kk-buf][mt][frag]
    uint32_t b[4][4];      // rolling [p][frag]

    for (int s = 0; s < 16; ++s) {
        if (s < 15) asm volatile("cp.async.wait_group 1;");
        else        asm volatile("cp.async.wait_group 0;");
        __syncthreads();

        const uint32_t stg = sb + (uint32_t)(s % 3) * STG_BYTES;
        const uint32_t nbo = (uint32_t)((s + 2) % 3) * STG_BYTES;
        const bool more = (s < 14);

        // fragments for kk=0
#pragma unroll
        for (int mt = 0; mt < 2; mt++) ldm4(a[0][mt], a_addr(stg, 0, mt));
#pragma unroll
        for (int p = 0; p < 4; p++)    ldm4(b[p],    b_addr(stg, 0, p));

#pragma unroll
        for (int kk = 0; kk < 4; kk++) {
            if (more) {
#pragma unroll
                for (int t = 0; t < 2; t++) {
                    const int i = kk * 2 + t;
                    if (i < 4) cp16(sa0 + nbo + i * 4096, aptr + (size_t)i * 32 * Edim);
                    else       cp16(sb0 + nbo + (i - 4) * 4096, bptr + (size_t)(i - 4) * 32 * Edim);
                }
            }
            const int cur = kk & 1;
            if (kk < 3) {
#pragma unroll
                for (int mt = 0; mt < 2; mt++)
                    ldm4(a[cur ^ 1][mt], a_addr(stg, kk + 1, mt));
            }
#pragma unroll
            for (int p = 0; p < 4; p++) {
#pragma unroll
                for (int q = 0; q < 2; q++) {
                    const int nt = 2 * p + q;
#pragma unroll
                    for (int mt = 0; mt < 2; mt++)
                        mma_f16(acc[mt][nt], a[cur][mt], b[p][q], b[p][q + 2]);
                }
                if (kk < 3) ldm4(b[p], b_addr(stg, kk + 1, p));
            }
        }
        if (more) {
            asm volatile("cp.async.commit_group;");
            aptr += 64;
            bptr += 64;
        }
    }

    // ---- epilogue: bias add ----
    const int g  = lane >> 2;
    const int q2 = (lane & 3) * 2;
#pragma unroll
    for (int mt = 0; mt < 2; mt++) {
#pragma unroll
        for (int h = 0; h < 2; h++) {
            const int row = brow + wm * 32 + mt * 16 + g + h * 8;
#pragma unroll
            for (int nt = 0; nt < 8; nt++) {
                const int col = bcol + wn * 64 + nt * 8 + q2;
                const float vx = acc[mt][nt][2 * h + 0] + __ldg(bias + col + 0);
                const float vy = acc[mt][nt][2 * h + 1] + __ldg(bias + col + 1);
                if (HALF_OUT) {
                    __half2 hv = __floats2half2_rn(vx, vy);
                    *(uint32_t*)((__half*)Cv + (size_t)row * N + col) = *(uint32_t*)&hv;
                } else {
                    float2 v2 = make_float2(vx, vy);
                    *(float2*)((float*)Cv + (size_t)row * N + col) = v2;
                }
            }
        }
    }
}

// ---------------------------------------------------------------------------
// Per-position "head attention" (einsum-label bug replicated exactly).
// 2 positions per 512-thread block (halves block count, amortizes syncs).
// Reads fp16 qkv, computes in fp32, emits fp16 output.
// ---------------------------------------------------------------------------
__global__ __launch_bounds__(512)
void attn_kernel(const __half* __restrict__ qkv, __half* __restrict__ oh)
{
    __shared__ __align__(16) float s[2][3 * Edim];
    __shared__ float en[2][Hh][Hh + 1];
    __shared__ float rinv[2][Hh];

    const int tid = threadIdx.x;
    const int pp  = tid >> 8;              // 0..1: which position this thread serves
    const int lt  = tid & 255;             // 0..255 within position group

    const int bp0 = blockIdx.x * 2;        // first position index (b*2048+pos)

    // load both positions' qkv rows: 2 x 768 uint2 over 512 threads = 3 iters
    {
#pragma unroll
        for (int t = 0; t < 3; t++) {
            const int idx = tid + t * 512;          // 0..1535
            const int p   = idx / 768;              // position select
            const int e   = idx - p * 768;          // 0..767
            const uint2* r2 = (const uint2*)(qkv + (size_t)(bp0 + p) * 3072);
            uint2 u = r2[e];
            __half2 h0 = *(__half2*)&u.x;
            __half2 h1 = *(__half2*)&u.y;
            float2 f0 = __half22float2(h0);
            float2 f1 = __half22float2(h1);
            ((float4*)s[p])[e] = make_float4(f0.x, f0.y, f1.x, f1.y);
        }
    }
    __syncthreads();

    // energy: 512 threads = 2 positions x 256 (i,j) pairs
    {
        const int i = lt >> 4;
        const int j = lt & 15;
        const float* q  = s[pp] + i * 64;
        const float* kp = s[pp] + 1024 + j * 64;
        float e = 0.f;
#pragma unroll
        for (int dd = 0; dd < 16; dd++) {
            const int d4 = ((dd + lt) & 15) * 4;
            float4 qv = *(const float4*)(q + d4);
            float4 kv = *(const float4*)(kp + d4);
            e += qv.x * kv.x + qv.y * kv.y + qv.z * kv.z + qv.w * kv.w;
        }
        en[pp][i][j] = e * 0.03125f;   // 1/sqrt(1024)
    }
    __syncthreads();

    // softmax: 32 threads handle 2 positions x 16 rows
    if (tid < 32) {
        const int p = tid >> 4;
        const int r = tid & 15;
        float m = -1e30f;
#pragma unroll
        for (int j = 0; j < Hh; j++) m = fmaxf(m, en[p][r][j]);
        float sum = 0.f;
#pragma unroll
        for (int j = 0; j < Hh; j++) {
            const float v = __expf(en[p][r][j] - m);
            en[p][r][j] = v;
            sum += v;
        }
        rinv[p][r] = 1.f / sum;
    }
    __syncthreads();

    // out: 2 positions x 1024 outputs over 512 threads = 4 per thread
    const int bpos = bp0 + pp;
    const int b    = bpos >> 11;
    const int pos  = bpos & 2047;
#pragma unroll
    for (int t0 = 0; t0 < 4; t0++) {
        const int t = lt + t0 * 256;
        const int i = t >> 6;
        const int d = t & 63;
        float o = 0.f;
#pragma unroll
        for (int l = 0; l < Hh; l++)
            o += en[pp][i][l] * s[pp][2048 + l * 64 + d];
        o *= rinv[pp][i];
        const size_t idx = ((size_t)(b * Hh + i) * Nseq + pos) * Dd + d;
        oh[idx] = __float2half_rn(o);
    }
}

// ---------------------------------------------------------------------------
// launch
// ---------------------------------------------------------------------------
extern "C" void kernel_launch(void* const* d_in, const int* in_sizes, int n_in,
                              void* d_out, int out_size)
{
    const float* x    = (const float*)d_in[0];   // [16384,1024]
    const float* Wqkv = (const float*)d_in[1];   // [3072,1024]
    const float* bqkv = (const float*)d_in[2];
    const float* Wo   = (const float*)d_in[3];   // [1024,1024]
    const float* bo   = (const float*)d_in[4];
    float* out = (float*)d_out;

    __half *qkvh, *xh, *ath, *wqh, *woh;
    cudaGetSymbolAddress((void**)&qkvh, g_qkvh);
    cudaGetSymbolAddress((void**)&xh,  g_xh);
    cudaGetSymbolAddress((void**)&ath, g_ath);
    cudaGetSymbolAddress((void**)&wqh, g_wqh);
    cudaGetSymbolAddress((void**)&woh, g_woh);

    cudaFuncSetAttribute(gemm_mma<true>,  cudaFuncAttributeMaxDynamicSharedMemorySize, GSMEM);
    cudaFuncSetAttribute(gemm_mma<false>, cudaFuncAttributeMaxDynamicSharedMemorySize, GSMEM);

    // 0) x, Wqkv, Wo -> fp16 in one launch
    tohalf3_kernel<<<(N4_TOTAL + 255) / 256, 256>>>(
        (const float4*)x,    (uint2*)xh,
        (const float4*)Wqkv, (uint2*)wqh,
        (const float4*)Wo,   (uint2*)woh);

    // 1) qkv = x @ Wqkv^T + bqkv   [16384, 3072]  (fp16 out)
    {
        dim3 grid(3 * Edim / 128, Mrows / 128);
        gemm_mma<true><<<grid, NTHREADS, GSMEM>>>(xh, wqh, bqkv, qkvh, 3 * Edim);
    }

    // 2) per-position head-attention -> fp16 in raw [B,H,N,D] layout
    attn_kernel<<<Mrows / 2, 512>>>(qkvh, ath);

    // 3) out = Y @ Wo^T + bo   [16384, 1024]  (fp32 out)
    {
        dim3 grid(Edim / 128, Mrows / 128);
        gemm_mma<false><<<grid, NTHREADS, GSMEM>>>(ath, woh, bo, out, Edim);
    }
}

// round 17
// speedup vs baseline: 1.2542x; 1.2104x over previous
#include <cuda_runtime.h>
#include <cuda_fp16.h>
#include <cstdint>

// Problem constants
#define Bdim 8
#define Nseq 2048
#define Edim 1024
#define Hh   16
#define Dd   64
#define Mrows (Bdim * Nseq)      // 16384

// ---------------------------------------------------------------------------
// Scratch (allocation-free rule: __device__ globals)
// ---------------------------------------------------------------------------
__device__ __half  g_qkvh[(size_t)Mrows * 3 * Edim];  // 96 MB fp16 qkv
__device__ __half  g_xh [(size_t)Mrows * Edim];       // x as fp16
__device__ __half  g_ath[(size_t)Mrows * Edim];       // attn out as fp16
__device__ __half  g_wqh[(size_t)3 * Edim * Edim];    // Wqkv fp16
__device__ __half  g_woh[(size_t)Edim * Edim];        // Wo fp16

// ---------------------------------------------------------------------------
// Helpers (baseline-feature PTX only: cp.async, ldmatrix, mma.sync — sm_80+)
// ---------------------------------------------------------------------------
__device__ __forceinline__ uint32_t smem_u32(const void* p) {
    uint32_t a;
    asm("{ .reg .u64 t; cvta.to.shared.u64 t, %1; cvt.u32.u64 %0, t; }" : "=r"(a) : "l"(p));
    return a;
}
#define SWZ(x) ((x) ^ (((x) >> 3) & 0x70))

__device__ __forceinline__ void cp16(uint32_t dst, const void* src) {
    asm volatile("cp.async.cg.shared.global [%0], [%1], 16;" :: "r"(dst), "l"(src));
}
__device__ __forceinline__ void ldm4(uint32_t* r, uint32_t addr) {
    asm volatile("ldmatrix.sync.aligned.m8n8.x4.shared.b16 {%0,%1,%2,%3}, [%4];"
                 : "=r"(r[0]), "=r"(r[1]), "=r"(r[2]), "=r"(r[3]) : "r"(addr));
}
__device__ __forceinline__ void ldm4t(uint32_t* r, uint32_t addr) {
    asm volatile("ldmatrix.sync.aligned.m8n8.x4.trans.shared.b16 {%0,%1,%2,%3}, [%4];"
                 : "=r"(r[0]), "=r"(r[1]), "=r"(r[2]), "=r"(r[3]) : "r"(addr));
}
__device__ __forceinline__ void mma_f16(float* c, const uint32_t* a, uint32_t b0, uint32_t b1) {
    asm volatile(
        "mma.sync.aligned.m16n8k16.row.col.f32.f16.f16.f32 "
        "{%0,%1,%2,%3}, {%4,%5,%6,%7}, {%8,%9}, {%0,%1,%2,%3};"
        : "+f"(c[0]), "+f"(c[1]), "+f"(c[2]), "+f"(c[3])
        : "r"(a[0]), "r"(a[1]), "r"(a[2]), "r"(a[3]), "r"(b0), "r"(b1));
}

// ---------------------------------------------------------------------------
// fp32 -> fp16 conversion, single launch, 3 segments (x | Wqkv | Wo)
// ---------------------------------------------------------------------------
#define N4_X  (Mrows * Edim / 4)
#define N4_WQ (3 * Edim * Edim / 4)
#define N4_WO (Edim * Edim / 4)
#define N4_TOTAL (N4_X + N4_WQ + N4_WO)

__global__ __launch_bounds__(256)
void tohalf3_kernel(const float4* __restrict__ sx, uint2* __restrict__ dx,
                    const float4* __restrict__ sq, uint2* __restrict__ dq,
                    const float4* __restrict__ so, uint2* __restrict__ dw)
{
    int i = blockIdx.x * 256 + threadIdx.x;
    const float4* src;
    uint2* dst;
    if (i < N4_X)                { src = sx; dst = dx; }
    else if (i < N4_X + N4_WQ)   { src = sq; dst = dq; i -= N4_X; }
    else if (i < N4_TOTAL)       { src = so; dst = dw; i -= (N4_X + N4_WQ); }
    else return;
    float4 v = src[i];
    __half2 p0 = __floats2half2_rn(v.x, v.y);
    __half2 p1 = __floats2half2_rn(v.z, v.w);
    uint2 u;
    u.x = *(uint32_t*)&p0; u.y = *(uint32_t*)&p1;
    dst[i] = u;
}

// ---------------------------------------------------------------------------
// fp16 NT GEMM via mma.sync (R14 best config, unchanged):
// CTA tile 128x128, 256 threads (8 warps 4x2, 32x64 per warp), K-slab 64.
// 3-stage cp.async ring (32KB/stage), 2 CTAs/SM.
// ---------------------------------------------------------------------------
#define STG_BYTES 32768
#define GSMEM (3 * STG_BYTES + 1024)
#define NTHREADS 256

template<bool HALF_OUT>
__global__ __launch_bounds__(NTHREADS, 2)
void gemm_mma(const __half* __restrict__ A, const __half* __restrict__ B,
              const float* __restrict__ bias, void* __restrict__ Cv, int N)
{
    extern __shared__ char smem_raw[];
    const uint32_t sb = (smem_u32(smem_raw) + 1023) & ~1023u;
    const int tid  = threadIdx.x;
    const int lane = tid & 31;
    const int wid  = tid >> 5;
    const int wm   = wid >> 1;
    const int wn   = wid & 1;
    const int brow = blockIdx.y * 128;
    const int bcol = blockIdx.x * 128;

    float acc[2][8][4];
#pragma unroll
    for (int i = 0; i < 2; i++)
#pragma unroll
        for (int j = 0; j < 8; j++)
#pragma unroll
            for (int k = 0; k < 4; k++) acc[i][j][k] = 0.f;

    const int  lrow   = lane & 15;
    const int  lkb    = (lane >> 4) * 16;
    const uint32_t a_base = SWZ((wm * 32 + lrow) * 128 + lkb);
    const uint32_t b_base = SWZ((wn * 64 + lrow) * 128 + lkb);

    const int r0 = tid >> 3;
    const int c8 = (tid & 7) * 8;
    const __half* aptr = A + (size_t)(brow + r0) * Edim + c8;
    const __half* bptr = B + (size_t)(bcol + r0) * Edim + c8;
    const uint32_t saw = SWZ(r0 * 128 + (tid & 7) * 16);
    const uint32_t sa0 = sb + saw;
    const uint32_t sb0 = sb + 16384 + saw;

    auto load_stage = [&](uint32_t bo) {
#pragma unroll
        for (int j = 0; j < 4; j++) {
            cp16(sa0 + bo + j * 4096, aptr + (size_t)j * 32 * Edim);
            cp16(sb0 + bo + j * 4096, bptr + (size_t)j * 32 * Edim);
        }
        asm volatile("cp.async.commit_group;");
        aptr += 64;
        bptr += 64;
    };

    load_stage(0);
    load_stage(STG_BYTES);

    auto a_addr = [&](uint32_t stg, int kk, int mt) {
        return stg + ((a_base + mt * 2048) ^ ((uint32_t)kk * 32));
    };
    auto b_addr = [&](uint32_t stg, int kk, int p) {
        return stg + 16384 + ((b_base + p * 2048) ^ ((uint32_t)kk * 32));
    };

    uint32_t a[2][2][4];
    uint32_t b[4][4];

    for (int s = 0; s < 16; ++s) {
        if (s < 15) asm volatile("cp.async.wait_group 1;");
        else        asm volatile("cp.async.wait_group 0;");
        __syncthreads();

        const uint32_t stg = sb + (uint32_t)(s % 3) * STG_BYTES;
        const uint32_t nbo = (uint32_t)((s + 2) % 3) * STG_BYTES;
        const bool more = (s < 14);

#pragma unroll
        for (int mt = 0; mt < 2; mt++) ldm4(a[0][mt], a_addr(stg, 0, mt));
#pragma unroll
        for (int p = 0; p < 4; p++)    ldm4(b[p],    b_addr(stg, 0, p));

#pragma unroll
        for (int kk = 0; kk < 4; kk++) {
            if (more) {
#pragma unroll
                for (int t = 0; t < 2; t++) {
                    const int i = kk * 2 + t;
                    if (i < 4) cp16(sa0 + nbo + i * 4096, aptr + (size_t)i * 32 * Edim);
                    else       cp16(sb0 + nbo + (i - 4) * 4096, bptr + (size_t)(i - 4) * 32 * Edim);
                }
            }
            const int cur = kk & 1;
            if (kk < 3) {
#pragma unroll
                for (int mt = 0; mt < 2; mt++)
                    ldm4(a[cur ^ 1][mt], a_addr(stg, kk + 1, mt));
            }
#pragma unroll
            for (int p = 0; p < 4; p++) {
#pragma unroll
                for (int q = 0; q < 2; q++) {
                    const int nt = 2 * p + q;
#pragma unroll
                    for (int mt = 0; mt < 2; mt++)
                        mma_f16(acc[mt][nt], a[cur][mt], b[p][q], b[p][q + 2]);
                }
                if (kk < 3) ldm4(b[p], b_addr(stg, kk + 1, p));
            }
        }
        if (more) {
            asm volatile("cp.async.commit_group;");
            aptr += 64;
            bptr += 64;
        }
    }

    const int g  = lane >> 2;
    const int q2 = (lane & 3) * 2;
#pragma unroll
    for (int mt = 0; mt < 2; mt++) {
#pragma unroll
        for (int h = 0; h < 2; h++) {
            const int row = brow + wm * 32 + mt * 16 + g + h * 8;
#pragma unroll
            for (int nt = 0; nt < 8; nt++) {
                const int col = bcol + wn * 64 + nt * 8 + q2;
                const float vx = acc[mt][nt][2 * h + 0] + __ldg(bias + col + 0);
                const float vy = acc[mt][nt][2 * h + 1] + __ldg(bias + col + 1);
                if (HALF_OUT) {
                    __half2 hv = __floats2half2_rn(vx, vy);
                    *(uint32_t*)((__half*)Cv + (size_t)row * N + col) = *(uint32_t*)&hv;
                } else {
                    float2 v2 = make_float2(vx, vy);
                    *(float2*)((float*)Cv + (size_t)row * N + col) = v2;
                }
            }
        }
    }
}

// ---------------------------------------------------------------------------
// Warp-per-position head-attention via HMMA (einsum-label bug replicated).
// energy[16,16] = q @ k^T (8 HMMA, K=64); softmax in registers (quad shfl);
// att accumulator layout == A-operand layout (no shuffle); out = att @ v via
// ldmatrix.trans B-fragments (8 HMMA). LDS per position ~8KB (was ~256KB).
// 8 warps (positions) per 256-thread block; 6KB smem per warp, SW128.
// ---------------------------------------------------------------------------
#define ATT_SMEM (8 * 6144 + 1024)

__global__ __launch_bounds__(256)
void attn_mma_kernel(const __half* __restrict__ qkv, __half* __restrict__ oh)
{
    extern __shared__ char smem_raw[];
    const uint32_t sb = (smem_u32(smem_raw) + 1023) & ~1023u;
    const int tid  = threadIdx.x;
    const int lane = tid & 31;
    const int wid  = tid >> 5;
    const int pg   = blockIdx.x * 8 + wid;      // position index (b*2048+pos)
    const int b    = pg >> 11;
    const int pos  = pg & 2047;
    const uint32_t wbase = sb + wid * 6144;     // 48 rows x 128B, SW128

    // load q|k|v (6KB contiguous) into swizzled smem
    {
        const __half* src = qkv + (size_t)pg * 3072;
#pragma unroll
        for (int i = 0; i < 12; i++) {
            const int chunk = lane + i * 32;
            cp16(wbase + SWZ(chunk * 16), src + chunk * 8);
        }
        asm volatile("cp.async.commit_group;");
        asm volatile("cp.async.wait_group 0;");
        __syncwarp();
    }

    const int lrow = lane & 15;
    const int lkb  = (lane >> 4) * 16;
    const uint32_t qb = wbase +        SWZ(lrow * 128 + lkb);   // q rows 0-15
    const uint32_t kb = wbase + 2048 + SWZ(lrow * 128 + lkb);   // k rows 0-15
    const uint32_t vb = wbase + 4096 + SWZ(lrow * 128 + lkb);   // v rows 0-15

    // ---- energy = q @ k^T  (fp32 acc; e0 = cols 0-7, e1 = cols 8-15) ----
    float e0[4] = {0.f, 0.f, 0.f, 0.f}, e1[4] = {0.f, 0.f, 0.f, 0.f};
#pragma unroll
    for (int kk = 0; kk < 4; kk++) {
        uint32_t af[4], bf[4];
        ldm4(af, qb ^ (uint32_t)(kk * 32));
        ldm4(bf, kb ^ (uint32_t)(kk * 32));
        mma_f16(e0, af, bf[0], bf[2]);
        mma_f16(e1, af, bf[1], bf[3]);
    }

    // ---- softmax over cols (scale 1/32); rows g=lane/4 (lo) and g+8 (hi) ----
#pragma unroll
    for (int i = 0; i < 4; i++) { e0[i] *= 0.03125f; e1[i] *= 0.03125f; }
    float mlo = fmaxf(fmaxf(e0[0], e0[1]), fmaxf(e1[0], e1[1]));
    float mhi = fmaxf(fmaxf(e0[2], e0[3]), fmaxf(e1[2], e1[3]));
#pragma unroll
    for (int o = 1; o < 4; o <<= 1) {
        mlo = fmaxf(mlo, __shfl_xor_sync(0xffffffff, mlo, o));
        mhi = fmaxf(mhi, __shfl_xor_sync(0xffffffff, mhi, o));
    }
    e0[0] = __expf(e0[0] - mlo); e0[1] = __expf(e0[1] - mlo);
    e1[0] = __expf(e1[0] - mlo); e1[1] = __expf(e1[1] - mlo);
    e0[2] = __expf(e0[2] - mhi); e0[3] = __expf(e0[3] - mhi);
    e1[2] = __expf(e1[2] - mhi); e1[3] = __expf(e1[3] - mhi);
    float slo = e0[0] + e0[1] + e1[0] + e1[1];
    float shi = e0[2] + e0[3] + e1[2] + e1[3];
#pragma unroll
    for (int o = 1; o < 4; o <<= 1) {
        slo += __shfl_xor_sync(0xffffffff, slo, o);
        shi += __shfl_xor_sync(0xffffffff, shi, o);
    }
    const float rlo = 1.f / slo, rhi = 1.f / shi;

    // att fragments: C-layout == A-operand layout (a0..a3)
    uint32_t af[4];
    {
        __half2 h;
        h = __floats2half2_rn(e0[0] * rlo, e0[1] * rlo); af[0] = *(uint32_t*)&h;
        h = __floats2half2_rn(e0[2] * rhi, e0[3] * rhi); af[1] = *(uint32_t*)&h;
        h = __floats2half2_rn(e1[0] * rlo, e1[1] * rlo); af[2] = *(uint32_t*)&h;
        h = __floats2half2_rn(e1[2] * rhi, e1[3] * rhi); af[3] = *(uint32_t*)&h;
    }

    // ---- out = att @ v  (8 n-tiles of 8 cols, k=16) ----
    float oacc[8][4];
#pragma unroll
    for (int j = 0; j < 8; j++)
#pragma unroll
        for (int k = 0; k < 4; k++) oacc[j][k] = 0.f;
#pragma unroll
    for (int nt = 0; nt < 4; nt++) {
        uint32_t bf[4];
        ldm4t(bf, vb ^ (uint32_t)(nt * 32));
        mma_f16(oacc[2 * nt + 0], af, bf[0], bf[1]);
        mma_f16(oacc[2 * nt + 1], af, bf[2], bf[3]);
    }

    // ---- store: out[i][d] at ((b*16+i)*2048+pos)*64 + d, fp16 ----
    const int g = lane >> 2;
    const int q = lane & 3;
    const size_t base_lo = ((size_t)(b * Hh + g) * Nseq + pos) * Dd;
    const size_t base_hi = base_lo + (size_t)8 * Nseq * Dd;
#pragma unroll
    for (int j = 0; j < 8; j++) {
        const int d = j * 8 + q * 2;
        __half2 lo = __floats2half2_rn(oacc[j][0], oacc[j][1]);
        __half2 hi = __floats2half2_rn(oacc[j][2], oacc[j][3]);
        *(uint32_t*)(oh + base_lo + d) = *(uint32_t*)&lo;
        *(uint32_t*)(oh + base_hi + d) = *(uint32_t*)&hi;
    }
}

// ---------------------------------------------------------------------------
// launch
// ---------------------------------------------------------------------------
extern "C" void kernel_launch(void* const* d_in, const int* in_sizes, int n_in,
                              void* d_out, int out_size)
{
    const float* x    = (const float*)d_in[0];   // [16384,1024]
    const float* Wqkv = (const float*)d_in[1];   // [3072,1024]
    const float* bqkv = (const float*)d_in[2];
    const float* Wo   = (const float*)d_in[3];   // [1024,1024]
    const float* bo   = (const float*)d_in[4];
    float* out = (float*)d_out;

    __half *qkvh, *xh, *ath, *wqh, *woh;
    cudaGetSymbolAddress((void**)&qkvh, g_qkvh);
    cudaGetSymbolAddress((void**)&xh,  g_xh);
    cudaGetSymbolAddress((void**)&ath, g_ath);
    cudaGetSymbolAddress((void**)&wqh, g_wqh);
    cudaGetSymbolAddress((void**)&woh, g_woh);

    cudaFuncSetAttribute(gemm_mma<true>,  cudaFuncAttributeMaxDynamicSharedMemorySize, GSMEM);
    cudaFuncSetAttribute(gemm_mma<false>, cudaFuncAttributeMaxDynamicSharedMemorySize, GSMEM);
    cudaFuncSetAttribute(attn_mma_kernel, cudaFuncAttributeMaxDynamicSharedMemorySize, ATT_SMEM);

    // 0) x, Wqkv, Wo -> fp16 in one launch
    tohalf3_kernel<<<(N4_TOTAL + 255) / 256, 256>>>(
        (const float4*)x,    (uint2*)xh,
        (const float4*)Wqkv, (uint2*)wqh,
        (const float4*)Wo,   (uint2*)woh);

    // 1) qkv = x @ Wqkv^T + bqkv   [16384, 3072]  (fp16 out)
    {
        dim3 grid(3 * Edim / 128, Mrows / 128);
        gemm_mma<true><<<grid, NTHREADS, GSMEM>>>(xh, wqh, bqkv, qkvh, 3 * Edim);
    }

    // 2) warp-per-position head-attention -> fp16 in raw [B,H,N,D] layout
    attn_mma_kernel<<<Mrows / 8, 256, ATT_SMEM>>>(qkvh, ath);

    // 3) out = Y @ Wo^T + bo   [16384, 1024]  (fp32 out)
    {
        dim3 grid(Edim / 128, Mrows / 128);
        gemm_mma<false><<<grid, NTHREADS, GSMEM>>>(ath, woh, bo, out, Edim);
    }
}